// round 1
// baseline (speedup 1.0000x reference)
#include <cuda_runtime.h>
#include <cuda_bf16.h>
#include <cstdint>

// Problem constants (fixed by setup_inputs)
#define BATCH 4
#define SEQ   2048
#define CDIM  1024
#define NHEAD 16
#define HDIM  64
#define MROWS (BATCH * SEQ)          // 8192
#define Y_ELEMS ((size_t)MROWS * CDIM)       // 8,388,608
#define KV_ELEMS ((size_t)BATCH * NHEAD * SEQ * HDIM) // 8,388,608

// Scratch (device globals: allocation-free per harness rules)
__device__ float g_q[Y_ELEMS];   // Q in [B,H,T,D]
__device__ float g_y[Y_ELEMS];   // attention output in [B,T,C]

// ---------------------------------------------------------------------------
// GEMM: out[m,n] = sum_k A[m,k] * W[n,k] + bias[n]
// A: [M,1024] row-major, W: [1024,1024] row-major (K contiguous for both).
// layout==0: out is [M,1024] row-major
// layout==1: out is [B,H,T,D] with m=b*T+t, n=h*D+d
// Tile 128x128x16, 256 threads, 8x8 per thread (split 64+64 fragments).
// ---------------------------------------------------------------------------
__global__ __launch_bounds__(256) void gemm_kernel(
    const float* __restrict__ A, const float* __restrict__ W,
    const float* __restrict__ bias, float* __restrict__ out, int layout)
{
    __shared__ float As[16][129];  // [k][m] transposed
    __shared__ float Bs[16][129];  // [k][n] transposed

    const int tid = threadIdx.x;
    const int tx = tid & 15;       // n group
    const int ty = tid >> 4;       // m group
    const int mbase = blockIdx.y * 128;
    const int nbase = blockIdx.x * 128;

    const float* Ap = A + (size_t)mbase * CDIM;
    const float* Wp = W + (size_t)nbase * CDIM;

    float acc[8][8];
    #pragma unroll
    for (int i = 0; i < 8; i++)
        #pragma unroll
        for (int j = 0; j < 8; j++) acc[i][j] = 0.f;

    for (int kk = 0; kk < CDIM; kk += 16) {
        #pragma unroll
        for (int it = 0; it < 8; it++) {
            int idx = tid + it * 256;       // 0..2047
            int k = idx & 15;
            int r = idx >> 4;               // 0..127
            As[k][r] = Ap[(size_t)r * CDIM + kk + k];
            Bs[k][r] = Wp[(size_t)r * CDIM + kk + k];
        }
        __syncthreads();
        #pragma unroll
        for (int k = 0; k < 16; k++) {
            float a[8], b[8];
            #pragma unroll
            for (int i = 0; i < 4; i++) {
                a[i]     = As[k][ty * 4 + i];
                a[i + 4] = As[k][64 + ty * 4 + i];
                b[i]     = Bs[k][tx * 4 + i];
                b[i + 4] = Bs[k][64 + tx * 4 + i];
            }
            #pragma unroll
            for (int i = 0; i < 8; i++)
                #pragma unroll
                for (int j = 0; j < 8; j++)
                    acc[i][j] += a[i] * b[j];
        }
        __syncthreads();
    }

    #pragma unroll
    for (int i = 0; i < 8; i++) {
        int ml = (i < 4) ? (ty * 4 + i) : (64 + ty * 4 + (i - 4));
        int m = mbase + ml;
        #pragma unroll
        for (int j = 0; j < 8; j++) {
            int nl = (j < 4) ? (tx * 4 + j) : (64 + tx * 4 + (j - 4));
            int n = nbase + nl;
            float v = acc[i][j] + bias[n];
            if (layout == 0) {
                out[(size_t)m * CDIM + n] = v;
            } else {
                int b_ = m >> 11;           // m / SEQ
                int t  = m & 2047;
                int h  = n >> 6;            // n / HDIM
                int d  = n & 63;
                out[(((size_t)(b_ * NHEAD + h)) * SEQ + t) * HDIM + d] = v;
            }
        }
    }
}

// ---------------------------------------------------------------------------
// Causal flash attention (fp32, online softmax).
// Q,K,V: [B*H][T][64]. Output Y: [B,T,C] (= [B,T,H*D]).
// Block: 64 q-rows x 64 k-cols per tile, D=64. 128 threads, 4x8 reg tiles.
// ---------------------------------------------------------------------------
__global__ __launch_bounds__(128) void attn_kernel(
    const float* __restrict__ Q, const float* __restrict__ K,
    const float* __restrict__ V, float* __restrict__ Y)
{
    __shared__ float Qs[64][65];   // [d][m], pre-scaled by 1/sqrt(D)
    __shared__ float Ks[64][65];   // [d][n]
    __shared__ float Ps[64][65];   // [n][m]
    __shared__ float Vs[64][65];   // [n][d]

    const int tid = threadIdx.x;
    const int tx = tid & 7;        // col group (n or d), 0..7, 8 cols each
    const int ty = tid >> 3;       // row group (m), 0..15, 4 rows each
    const int qt = blockIdx.x;     // q tile index (0..31)
    const int bh = blockIdx.y;     // b*H + h
    const int qbase = qt * 64;

    const float* Qp = Q + (size_t)bh * SEQ * HDIM + (size_t)qbase * HDIM;
    const float* Kp = K + (size_t)bh * SEQ * HDIM;
    const float* Vp = V + (size_t)bh * SEQ * HDIM;

    // Load Q tile transposed + scaled
    for (int idx = tid; idx < 64 * 64; idx += 128) {
        int d = idx & 63, m = idx >> 6;
        Qs[d][m] = Qp[idx] * 0.125f;   // 1/sqrt(64)
    }

    float o[4][8];
    float mi[4], li[4];
    #pragma unroll
    for (int i = 0; i < 4; i++) {
        mi[i] = -1e30f; li[i] = 0.f;
        #pragma unroll
        for (int j = 0; j < 8; j++) o[i][j] = 0.f;
    }

    for (int jt = 0; jt <= qt; jt++) {
        __syncthreads();   // previous O-GEMM done with Ps/Vs/Ks
        const float* Kt = Kp + (size_t)jt * 64 * HDIM;
        const float* Vt = Vp + (size_t)jt * 64 * HDIM;
        for (int idx = tid; idx < 64 * 64; idx += 128) {
            int d = idx & 63, n = idx >> 6;
            Ks[d][n] = Kt[idx];
            Vs[n][d] = Vt[idx];
        }
        __syncthreads();

        // S = Qs^T * Ks  (64x64), each thread 4x8
        float s[4][8];
        #pragma unroll
        for (int i = 0; i < 4; i++)
            #pragma unroll
            for (int j = 0; j < 8; j++) s[i][j] = 0.f;

        #pragma unroll 8
        for (int d = 0; d < 64; d++) {
            float a[4], b[8];
            #pragma unroll
            for (int i = 0; i < 4; i++) a[i] = Qs[d][ty * 4 + i];
            #pragma unroll
            for (int j = 0; j < 8; j++) b[j] = Ks[d][tx * 8 + j];
            #pragma unroll
            for (int i = 0; i < 4; i++)
                #pragma unroll
                for (int j = 0; j < 8; j++)
                    s[i][j] += a[i] * b[j];
        }

        // Causal mask only on the diagonal tile
        if (jt == qt) {
            #pragma unroll
            for (int i = 0; i < 4; i++) {
                int ml = ty * 4 + i;
                #pragma unroll
                for (int j = 0; j < 8; j++) {
                    int nl = tx * 8 + j;
                    if (nl > ml) s[i][j] = -1e30f;
                }
            }
        }

        // Online softmax
        #pragma unroll
        for (int i = 0; i < 4; i++) {
            float rm = s[i][0];
            #pragma unroll
            for (int j = 1; j < 8; j++) rm = fmaxf(rm, s[i][j]);
            #pragma unroll
            for (int off = 1; off < 8; off <<= 1)
                rm = fmaxf(rm, __shfl_xor_sync(0xffffffffu, rm, off));
            float mn = fmaxf(mi[i], rm);
            float c = __expf(mi[i] - mn);
            float rs = 0.f;
            #pragma unroll
            for (int j = 0; j < 8; j++) {
                float p = __expf(s[i][j] - mn);
                s[i][j] = p;
                rs += p;
            }
            #pragma unroll
            for (int off = 1; off < 8; off <<= 1)
                rs += __shfl_xor_sync(0xffffffffu, rs, off);
            li[i] = li[i] * c + rs;
            mi[i] = mn;
            #pragma unroll
            for (int j = 0; j < 8; j++) o[i][j] *= c;
        }

        // Write P transposed [n][m]
        #pragma unroll
        for (int i = 0; i < 4; i++)
            #pragma unroll
            for (int j = 0; j < 8; j++)
                Ps[tx * 8 + j][ty * 4 + i] = s[i][j];
        __syncthreads();

        // O += P * V  (loop over n)
        #pragma unroll 8
        for (int n = 0; n < 64; n++) {
            float p[4], v[8];
            #pragma unroll
            for (int i = 0; i < 4; i++) p[i] = Ps[n][ty * 4 + i];
            #pragma unroll
            for (int j = 0; j < 8; j++) v[j] = Vs[n][tx * 8 + j];
            #pragma unroll
            for (int i = 0; i < 4; i++)
                #pragma unroll
                for (int j = 0; j < 8; j++)
                    o[i][j] += p[i] * v[j];
        }
    }

    // Normalize and write to [B,T,C]
    const int b_ = bh >> 4;
    const int h  = bh & 15;
    #pragma unroll
    for (int i = 0; i < 4; i++) {
        int t = qbase + ty * 4 + i;
        float inv = 1.f / li[i];
        size_t row = ((size_t)b_ * SEQ + t) * CDIM + (size_t)h * HDIM;
        #pragma unroll
        for (int j = 0; j < 8; j++)
            Y[row + tx * 8 + j] = o[i][j] * inv;
    }
}

// ---------------------------------------------------------------------------
// Launch: QKV GEMMs -> flash attention -> output projection.
// d_in order: x, Wq, bq, Wk, bk, Wv, bv, Wp, bp
// d_out: [ y (B*T*C) | present_k (B*H*T*D) | present_v (B*H*T*D) ]
// ---------------------------------------------------------------------------
extern "C" void kernel_launch(void* const* d_in, const int* in_sizes, int n_in,
                              void* d_out, int out_size)
{
    const float* x  = (const float*)d_in[0];
    const float* Wq = (const float*)d_in[1];
    const float* bq = (const float*)d_in[2];
    const float* Wk = (const float*)d_in[3];
    const float* bk = (const float*)d_in[4];
    const float* Wv = (const float*)d_in[5];
    const float* bv = (const float*)d_in[6];
    const float* Wp = (const float*)d_in[7];
    const float* bp = (const float*)d_in[8];

    float* out  = (float*)d_out;
    float* kout = out + Y_ELEMS;              // present[0] = k, [B,H,T,D]
    float* vout = out + Y_ELEMS + KV_ELEMS;   // present[1] = v

    float *qp = nullptr, *yp = nullptr;
    cudaGetSymbolAddress((void**)&qp, g_q);
    cudaGetSymbolAddress((void**)&yp, g_y);

    dim3 gg(CDIM / 128, MROWS / 128);   // (8, 64)
    gemm_kernel<<<gg, 256>>>(x, Wq, bq, qp,   1);
    gemm_kernel<<<gg, 256>>>(x, Wk, bk, kout, 1);
    gemm_kernel<<<gg, 256>>>(x, Wv, bv, vout, 1);

    attn_kernel<<<dim3(SEQ / 64, BATCH * NHEAD), 128>>>(qp, kout, vout, yp);

    gemm_kernel<<<gg, 256>>>(yp, Wp, bp, out, 0);
}